// round 9
// baseline (speedup 1.0000x reference)
#include <cuda_runtime.h>

#define CN0 50000
#define CN1 150000
#define CN2 20000
#define CN3 5000
#define CN4 1000
#define CE0 800000
#define CE1 1500000
#define CNNZ 300000
#define DD 64

// mega-scatter geometry: 26 block-slots per group, 6250 groups
//   r in [0,15)  -> E1 blocks : 15*6250 = 93750 blocks * 16 edges = 1.5M  (== CE1)
//   r in [15,23) -> E0 blocks :  8*6250 = 50000 blocks * 16 edges = 800k  (== CE0)
//   r in [23,26) -> inc blocks:  3*6250 = 18750 blocks * 16 edges = 300k  (== CNNZ)
#define MEGA_GRID 162500

// ---------------- scratch (static device globals; no allocation) ----------------
__device__ float g_m0[CN0 * DD];
__device__ float g_m1[CN1 * DD];
__device__ float g_ms[CN1 * DD];
__device__ float g_mt[CN0 * DD];
__device__ float g_accA0[CN0 * DD];
__device__ float g_accB0[CN0 * DD];
__device__ float g_accA1[CN1 * DD];
__device__ float g_accB1[CN1 * DD];

// ---------------- packed f32x2 helpers (Blackwell FFMA2) ----------------
__device__ __forceinline__ unsigned long long pack2(float x, float y) {
    unsigned long long r;
    asm("mov.b64 %0, {%1,%2};" : "=l"(r) : "f"(x), "f"(y));
    return r;
}
__device__ __forceinline__ void fma2(unsigned long long& d, unsigned long long a,
                                     unsigned long long b) {
    asm("fma.rn.f32x2 %0, %1, %2, %0;" : "+l"(d) : "l"(a), "l"(b));
}
__device__ __forceinline__ float2 unpack2(unsigned long long v) {
    float2 f;
    asm("mov.b64 {%0,%1}, %2;" : "=f"(f.x), "=f"(f.y) : "l"(v));
    return f;
}

// =====================================================================
// Dual GEMM: out1 = X@W1, out2 = X@W2.  128 rows/block, 256 threads.
// =====================================================================
__global__ __launch_bounds__(256) void gemm64_dual(const float* __restrict__ X,
                                                   const float* __restrict__ W1,
                                                   const float* __restrict__ W2,
                                                   float* __restrict__ out1,
                                                   float* __restrict__ out2, int N) {
    __shared__ __align__(16) float sW1[64 * 64];
    __shared__ __align__(16) float sW2[64 * 64];
    __shared__ __align__(16) float sXT[128 * 64];
    int tid = threadIdx.x;
#pragma unroll
    for (int i = 0; i < 16; i++) {
        sW1[tid + i * 256] = W1[tid + i * 256];
        sW2[tid + i * 256] = W2[tid + i * 256];
    }
    long r0 = (long)blockIdx.x * 128;
#pragma unroll
    for (int i = 0; i < 32; i++) {
        int li = tid + i * 256;
        int row = li >> 6, col = li & 63;
        long gr = r0 + row;
        float v = (gr < N) ? X[gr * 64 + col] : 0.f;
        sXT[col * 128 + (((row >> 2) ^ (col & 31)) << 2) + (row & 3)] = v;
    }
    __syncthreads();

    int tx = tid & 15, ty = tid >> 4;
    unsigned long long a1[8][2], a2[8][2];
#pragma unroll
    for (int r = 0; r < 8; r++) { a1[r][0] = a1[r][1] = a2[r][0] = a2[r][1] = 0ull; }

    const float4* sXT4 = (const float4*)sXT;
    const ulonglong2* sW1v = (const ulonglong2*)sW1;
    const ulonglong2* sW2v = (const ulonglong2*)sW2;
    int g0 = 2 * ty, g1 = 2 * ty + 1;
#pragma unroll 8
    for (int k = 0; k < 64; k++) {
        float4 xa = sXT4[k * 32 + (g0 ^ (k & 31))];
        float4 xb = sXT4[k * 32 + (g1 ^ (k & 31))];
        ulonglong2 w1 = sW1v[k * 16 + tx];
        ulonglong2 w2 = sW2v[k * 16 + tx];
        float xs[8] = {xa.x, xa.y, xa.z, xa.w, xb.x, xb.y, xb.z, xb.w};
#pragma unroll
        for (int r = 0; r < 8; r++) {
            unsigned long long xx = pack2(xs[r], xs[r]);
            fma2(a1[r][0], xx, w1.x); fma2(a1[r][1], xx, w1.y);
            fma2(a2[r][0], xx, w2.x); fma2(a2[r][1], xx, w2.y);
        }
    }
#pragma unroll
    for (int r = 0; r < 8; r++) {
        long row = r0 + ty * 8 + r;
        if (row < N) {
            float2 lo = unpack2(a1[r][0]), hi = unpack2(a1[r][1]);
            ((float4*)out1)[row * 16 + tx] = make_float4(lo.x, lo.y, hi.x, hi.y);
            lo = unpack2(a2[r][0]); hi = unpack2(a2[r][1]);
            ((float4*)out2)[row * 16 + tx] = make_float4(lo.x, lo.y, hi.x, hi.y);
        }
    }
}

// =====================================================================
// Fused epilogue: out = relu((relu(A)+relu(B)) @ W)
// =====================================================================
__global__ __launch_bounds__(256) void gemm64_fused(const float* __restrict__ A,
                                                    const float* __restrict__ B,
                                                    const float* __restrict__ W,
                                                    float* __restrict__ out, int N) {
    __shared__ __align__(16) float sW[64 * 64];
    __shared__ __align__(16) float sXT[128 * 64];
    int tid = threadIdx.x;
#pragma unroll
    for (int i = 0; i < 16; i++) sW[tid + i * 256] = W[tid + i * 256];
    long r0 = (long)blockIdx.x * 128;
#pragma unroll
    for (int i = 0; i < 32; i++) {
        int li = tid + i * 256;
        int row = li >> 6, col = li & 63;
        long gr = r0 + row;
        float v = 0.f;
        if (gr < N) {
            long idx = gr * 64 + col;
            v = fmaxf(A[idx], 0.f) + fmaxf(B[idx], 0.f);
        }
        sXT[col * 128 + (((row >> 2) ^ (col & 31)) << 2) + (row & 3)] = v;
    }
    __syncthreads();

    int tx = tid & 15, ty = tid >> 4;
    unsigned long long a1[8][2];
#pragma unroll
    for (int r = 0; r < 8; r++) { a1[r][0] = a1[r][1] = 0ull; }

    const float4* sXT4 = (const float4*)sXT;
    const ulonglong2* sWv = (const ulonglong2*)sW;
    int g0 = 2 * ty, g1 = 2 * ty + 1;
#pragma unroll 8
    for (int k = 0; k < 64; k++) {
        float4 xa = sXT4[k * 32 + (g0 ^ (k & 31))];
        float4 xb = sXT4[k * 32 + (g1 ^ (k & 31))];
        ulonglong2 w = sWv[k * 16 + tx];
        float xs[8] = {xa.x, xa.y, xa.z, xa.w, xb.x, xb.y, xb.z, xb.w};
#pragma unroll
        for (int r = 0; r < 8; r++) {
            unsigned long long xx = pack2(xs[r], xs[r]);
            fma2(a1[r][0], xx, w.x); fma2(a1[r][1], xx, w.y);
        }
    }
#pragma unroll
    for (int r = 0; r < 8; r++) {
        long row = r0 + ty * 8 + r;
        if (row < N) {
            float2 lo = unpack2(a1[r][0]), hi = unpack2(a1[r][1]);
            ((float4*)out)[row * 16 + tx] =
                make_float4(fmaxf(lo.x, 0.f), fmaxf(lo.y, 0.f),
                            fmaxf(hi.x, 0.f), fmaxf(hi.y, 0.f));
        }
    }
}

// =====================================================================
// Mega scatter: all three scatter types in one launch, interleaved by
// blockIdx so every wave carries a 15:8:3 mix of E1:E0:inc blocks.
// Each block: 16 edges; metadata staged in smem once (threads 0-15).
// =====================================================================
__global__ __launch_bounds__(256) void mega_scatter(
    const float* __restrict__ m0, const float* __restrict__ m1,
    const float* __restrict__ ms, const float* __restrict__ mt,
    const int* __restrict__ adj0, const float* __restrict__ adj0v,
    const float* __restrict__ cci0, const float* __restrict__ a0,
    const int* __restrict__ adj1, const float* __restrict__ adj1v,
    const float* __restrict__ cci1, const float* __restrict__ a1,
    const int* __restrict__ inc, const float* __restrict__ incv,
    float* __restrict__ accA0, float* __restrict__ accA1,
    float* __restrict__ accB0, float* __restrict__ accB1) {
    __shared__ int s_src[16];
    __shared__ int s_dst[16];
    __shared__ float s_c[16];
    int b = blockIdx.x;
    int g = b / 26;
    int r = b - g * 26;
    int tid = threadIdx.x;

    if (r < 23) {
        // ---- adjacency scatter (E1 if r<15, else E0) ----
        bool is1 = (r < 15);
        const int* adj = is1 ? adj1 : adj0;
        const float* val = is1 ? adj1v : adj0v;
        const float* cci = is1 ? cci1 : cci0;
        const float* av = is1 ? a1 : a0;
        const float* m = is1 ? m1 : m0;
        float* acc = is1 ? accA1 : accA0;
        int Eoff = is1 ? CE1 : CE0;
        int blk = is1 ? (g * 15 + r) : (g * 8 + (r - 15));
        int ebase = blk * 16;
        if (tid < 16) {
            int e = ebase + tid;
            s_src[tid] = adj[e];
            s_dst[tid] = adj[Eoff + e];
            s_c[tid] = val[e] * (cci[e * 3 + 0] * av[0] + cci[e * 3 + 1] * av[1] +
                                 cci[e * 3 + 2] * av[2]);
        }
        __syncthreads();
        int le = tid >> 4, sub = tid & 15;
        float c = s_c[le];
        float4 v = reinterpret_cast<const float4*>(m + (long)s_src[le] * 64)[sub];
        v.x *= c; v.y *= c; v.z *= c; v.w *= c;
        float* p = acc + (long)s_dst[le] * 64 + sub * 4;
        asm volatile("red.global.add.v4.f32 [%0], {%1,%2,%3,%4};"
                     :: "l"(p), "f"(v.x), "f"(v.y), "f"(v.z), "f"(v.w) : "memory");
    } else {
        // ---- incidence scatter (both directions) ----
        int blk = g * 3 + (r - 23);
        int ebase = blk * 16;
        if (tid < 16) {
            int e = ebase + tid;
            s_src[tid] = inc[e];          // row -> index into x0 side
            s_dst[tid] = inc[CNNZ + e];   // col -> index into x1 side
            s_c[tid] = incv[e];
        }
        __syncthreads();
        int le = tid >> 4, sub = tid & 15;
        int rw = s_src[le];
        int cl = s_dst[le];
        float v = s_c[le];
        // accB0[row] += v * ms[col]
        float4 a = reinterpret_cast<const float4*>(ms + (long)cl * 64)[sub];
        a.x *= v; a.y *= v; a.z *= v; a.w *= v;
        float* p0 = accB0 + (long)rw * 64 + sub * 4;
        asm volatile("red.global.add.v4.f32 [%0], {%1,%2,%3,%4};"
                     :: "l"(p0), "f"(a.x), "f"(a.y), "f"(a.z), "f"(a.w) : "memory");
        // accB1[col] += v * mt[row]
        float4 bq = reinterpret_cast<const float4*>(mt + (long)rw * 64)[sub];
        bq.x *= v; bq.y *= v; bq.z *= v; bq.w *= v;
        float* p1 = accB1 + (long)cl * 64 + sub * 4;
        asm volatile("red.global.add.v4.f32 [%0], {%1,%2,%3,%4};"
                     :: "l"(p1), "f"(bq.x), "f"(bq.y), "f"(bq.z), "f"(bq.w) : "memory");
    }
}

// ---------------- stream/event pool: LAZY init on first kernel_launch ----------------
static cudaStream_t s1 = 0, s2 = 0, s3 = 0;
static cudaEvent_t eRoot = 0, eZ = 0, eG0 = 0, eS = 0, eF0 = 0, eC = 0;
static int g_init_state = 0;  // 0 = untried, 1 = ok, -1 = failed (serial fallback)

static void ensure_init() {
    if (g_init_state != 0) return;
    bool ok = true;
    ok &= (cudaStreamCreateWithFlags(&s1, cudaStreamNonBlocking) == cudaSuccess);
    ok &= (cudaStreamCreateWithFlags(&s2, cudaStreamNonBlocking) == cudaSuccess);
    ok &= (cudaStreamCreateWithFlags(&s3, cudaStreamNonBlocking) == cudaSuccess);
    ok &= (cudaEventCreateWithFlags(&eRoot, cudaEventDisableTiming) == cudaSuccess);
    ok &= (cudaEventCreateWithFlags(&eZ, cudaEventDisableTiming) == cudaSuccess);
    ok &= (cudaEventCreateWithFlags(&eG0, cudaEventDisableTiming) == cudaSuccess);
    ok &= (cudaEventCreateWithFlags(&eS, cudaEventDisableTiming) == cudaSuccess);
    ok &= (cudaEventCreateWithFlags(&eF0, cudaEventDisableTiming) == cudaSuccess);
    ok &= (cudaEventCreateWithFlags(&eC, cudaEventDisableTiming) == cudaSuccess);
    g_init_state = ok ? 1 : -1;
}

// ---------------- launch ----------------
extern "C" void kernel_launch(void* const* d_in, const int* in_sizes, int n_in,
                              void* d_out, int out_size) {
    ensure_init();

    const float* x0   = (const float*)d_in[0];
    const float* x1   = (const float*)d_in[1];
    const float* x2   = (const float*)d_in[2];
    const float* x3   = (const float*)d_in[3];
    const float* x4   = (const float*)d_in[4];
    const int*   adj0 = (const int*)d_in[5];
    const float* adj0v= (const float*)d_in[6];
    const int*   adj1 = (const int*)d_in[7];
    const float* adj1v= (const float*)d_in[8];
    const int*   inc  = (const int*)d_in[9];
    const float* incv = (const float*)d_in[10];
    const float* cci0 = (const float*)d_in[11];
    const float* cci1 = (const float*)d_in[12];
    const float* Whbs0= (const float*)d_in[13];
    const float* ahbs0= (const float*)d_in[14];
    const float* Whbs1= (const float*)d_in[15];
    const float* ahbs1= (const float*)d_in[16];
    const float* Ws   = (const float*)d_in[17];
    const float* Wt   = (const float*)d_in[18];
    const float* Wag0 = (const float*)d_in[19];
    const float* Wag1 = (const float*)d_in[20];
    float* out = (float*)d_out;

    float *pm0, *pm1, *pms, *pmt, *pA0, *pB0, *pA1, *pB1;
    cudaGetSymbolAddress((void**)&pm0, g_m0);
    cudaGetSymbolAddress((void**)&pm1, g_m1);
    cudaGetSymbolAddress((void**)&pms, g_ms);
    cudaGetSymbolAddress((void**)&pmt, g_mt);
    cudaGetSymbolAddress((void**)&pA0, g_accA0);
    cudaGetSymbolAddress((void**)&pB0, g_accB0);
    cudaGetSymbolAddress((void**)&pA1, g_accA1);
    cudaGetSymbolAddress((void**)&pB1, g_accB1);

    if (g_init_state == 1) {
        // ---- fork ----
        cudaEventRecord(eRoot, 0);
        cudaStreamWaitEvent(s1, eRoot, 0);
        cudaStreamWaitEvent(s2, eRoot, 0);
        cudaStreamWaitEvent(s3, eRoot, 0);

        // s2: zero all accumulators
        cudaMemsetAsync(pA1, 0, sizeof(float) * (size_t)CN1 * DD, s2);
        cudaMemsetAsync(pB1, 0, sizeof(float) * (size_t)CN1 * DD, s2);
        cudaMemsetAsync(pA0, 0, sizeof(float) * (size_t)CN0 * DD, s2);
        cudaMemsetAsync(pB0, 0, sizeof(float) * (size_t)CN0 * DD, s2);
        cudaEventRecord(eZ, s2);

        // s1: gemm(x0); main: gemm(x1)
        gemm64_dual<<<(CN0 + 127) / 128, 256, 0, s1>>>(x0, Whbs0, Wt, pm0, pmt, CN0);
        cudaEventRecord(eG0, s1);
        gemm64_dual<<<(CN1 + 127) / 128, 256, 0, 0>>>(x1, Whbs1, Ws, pm1, pms, CN1);

        // s3: pass-through copies (fully independent)
        cudaMemcpyAsync(out + (long)(CN0 + CN1) * DD, x2, sizeof(float) * (size_t)CN2 * DD,
                        cudaMemcpyDeviceToDevice, s3);
        cudaMemcpyAsync(out + (long)(CN0 + CN1 + CN2) * DD, x3, sizeof(float) * (size_t)CN3 * DD,
                        cudaMemcpyDeviceToDevice, s3);
        cudaMemcpyAsync(out + (long)(CN0 + CN1 + CN2 + CN3) * DD, x4,
                        sizeof(float) * (size_t)CN4 * DD, cudaMemcpyDeviceToDevice, s3);
        cudaEventRecord(eC, s3);

        // main: mega-scatter after {gemm1 (in-stream), gemm0, memsets}
        cudaStreamWaitEvent(0, eG0, 0);
        cudaStreamWaitEvent(0, eZ, 0);
        mega_scatter<<<MEGA_GRID, 256, 0, 0>>>(pm0, pm1, pms, pmt,
                                               adj0, adj0v, cci0, ahbs0,
                                               adj1, adj1v, cci1, ahbs1,
                                               inc, incv, pA0, pA1, pB0, pB1);
        cudaEventRecord(eS, 0);

        // epilogues: fused0 on s1, fused1 on main
        cudaStreamWaitEvent(s1, eS, 0);
        gemm64_fused<<<(CN0 + 127) / 128, 256, 0, s1>>>(pA0, pB0, Wag0, out, CN0);
        cudaEventRecord(eF0, s1);
        gemm64_fused<<<(CN1 + 127) / 128, 256, 0, 0>>>(pA1, pB1, Wag1,
                                                       out + (long)CN0 * DD, CN1);
        // join
        cudaStreamWaitEvent(0, eF0, 0);
        cudaStreamWaitEvent(0, eC, 0);
    } else {
        // ---- serial fallback ----
        cudaMemsetAsync(pA0, 0, sizeof(float) * (size_t)CN0 * DD);
        cudaMemsetAsync(pB0, 0, sizeof(float) * (size_t)CN0 * DD);
        cudaMemsetAsync(pA1, 0, sizeof(float) * (size_t)CN1 * DD);
        cudaMemsetAsync(pB1, 0, sizeof(float) * (size_t)CN1 * DD);
        gemm64_dual<<<(CN0 + 127) / 128, 256>>>(x0, Whbs0, Wt, pm0, pmt, CN0);
        gemm64_dual<<<(CN1 + 127) / 128, 256>>>(x1, Whbs1, Ws, pm1, pms, CN1);
        mega_scatter<<<MEGA_GRID, 256>>>(pm0, pm1, pms, pmt,
                                         adj0, adj0v, cci0, ahbs0,
                                         adj1, adj1v, cci1, ahbs1,
                                         inc, incv, pA0, pA1, pB0, pB1);
        gemm64_fused<<<(CN0 + 127) / 128, 256>>>(pA0, pB0, Wag0, out, CN0);
        gemm64_fused<<<(CN1 + 127) / 128, 256>>>(pA1, pB1, Wag1, out + (long)CN0 * DD, CN1);
        cudaMemcpyAsync(out + (long)(CN0 + CN1) * DD, x2, sizeof(float) * (size_t)CN2 * DD,
                        cudaMemcpyDeviceToDevice);
        cudaMemcpyAsync(out + (long)(CN0 + CN1 + CN2) * DD, x3, sizeof(float) * (size_t)CN3 * DD,
                        cudaMemcpyDeviceToDevice);
        cudaMemcpyAsync(out + (long)(CN0 + CN1 + CN2 + CN3) * DD, x4,
                        sizeof(float) * (size_t)CN4 * DD, cudaMemcpyDeviceToDevice);
    }
}

// round 10
// speedup vs baseline: 1.2931x; 1.2931x over previous
#include <cuda_runtime.h>

#define CN0 50000
#define CN1 150000
#define CN2 20000
#define CN3 5000
#define CN4 1000
#define CE0 800000
#define CE1 1500000
#define CNNZ 300000
#define DD 64

// ---------------- scratch (static device globals; no allocation) ----------------
__device__ float g_m0[CN0 * DD];
__device__ float g_m1[CN1 * DD];
__device__ float g_ms[CN1 * DD];
__device__ float g_mt[CN0 * DD];
__device__ float g_accA0[CN0 * DD];
__device__ float g_accB0[CN0 * DD];
__device__ float g_accA1[CN1 * DD];
__device__ float g_accB1[CN1 * DD];

// ---------------- packed f32x2 helpers (Blackwell FFMA2) ----------------
__device__ __forceinline__ unsigned long long pack2(float x, float y) {
    unsigned long long r;
    asm("mov.b64 %0, {%1,%2};" : "=l"(r) : "f"(x), "f"(y));
    return r;
}
__device__ __forceinline__ void fma2(unsigned long long& d, unsigned long long a,
                                     unsigned long long b) {
    asm("fma.rn.f32x2 %0, %1, %2, %0;" : "+l"(d) : "l"(a), "l"(b));
}
__device__ __forceinline__ float2 unpack2(unsigned long long v) {
    float2 f;
    asm("mov.b64 {%0,%1}, %2;" : "=f"(f.x), "=f"(f.y) : "l"(v));
    return f;
}

// =====================================================================
// Dual GEMM: out1 = X@W1, out2 = X@W2.  128 rows/block, 256 threads.
// =====================================================================
__global__ __launch_bounds__(256) void gemm64_dual(const float* __restrict__ X,
                                                   const float* __restrict__ W1,
                                                   const float* __restrict__ W2,
                                                   float* __restrict__ out1,
                                                   float* __restrict__ out2, int N) {
    __shared__ __align__(16) float sW1[64 * 64];
    __shared__ __align__(16) float sW2[64 * 64];
    __shared__ __align__(16) float sXT[128 * 64];
    int tid = threadIdx.x;
#pragma unroll
    for (int i = 0; i < 16; i++) {
        sW1[tid + i * 256] = W1[tid + i * 256];
        sW2[tid + i * 256] = W2[tid + i * 256];
    }
    long r0 = (long)blockIdx.x * 128;
#pragma unroll
    for (int i = 0; i < 32; i++) {
        int li = tid + i * 256;
        int row = li >> 6, col = li & 63;
        long gr = r0 + row;
        float v = (gr < N) ? X[gr * 64 + col] : 0.f;
        sXT[col * 128 + (((row >> 2) ^ (col & 31)) << 2) + (row & 3)] = v;
    }
    __syncthreads();

    int tx = tid & 15, ty = tid >> 4;
    unsigned long long a1[8][2], a2[8][2];
#pragma unroll
    for (int r = 0; r < 8; r++) { a1[r][0] = a1[r][1] = a2[r][0] = a2[r][1] = 0ull; }

    const float4* sXT4 = (const float4*)sXT;
    const ulonglong2* sW1v = (const ulonglong2*)sW1;
    const ulonglong2* sW2v = (const ulonglong2*)sW2;
    int g0 = 2 * ty, g1 = 2 * ty + 1;
#pragma unroll 8
    for (int k = 0; k < 64; k++) {
        float4 xa = sXT4[k * 32 + (g0 ^ (k & 31))];
        float4 xb = sXT4[k * 32 + (g1 ^ (k & 31))];
        ulonglong2 w1 = sW1v[k * 16 + tx];
        ulonglong2 w2 = sW2v[k * 16 + tx];
        float xs[8] = {xa.x, xa.y, xa.z, xa.w, xb.x, xb.y, xb.z, xb.w};
#pragma unroll
        for (int r = 0; r < 8; r++) {
            unsigned long long xx = pack2(xs[r], xs[r]);
            fma2(a1[r][0], xx, w1.x); fma2(a1[r][1], xx, w1.y);
            fma2(a2[r][0], xx, w2.x); fma2(a2[r][1], xx, w2.y);
        }
    }
#pragma unroll
    for (int r = 0; r < 8; r++) {
        long row = r0 + ty * 8 + r;
        if (row < N) {
            float2 lo = unpack2(a1[r][0]), hi = unpack2(a1[r][1]);
            ((float4*)out1)[row * 16 + tx] = make_float4(lo.x, lo.y, hi.x, hi.y);
            lo = unpack2(a2[r][0]); hi = unpack2(a2[r][1]);
            ((float4*)out2)[row * 16 + tx] = make_float4(lo.x, lo.y, hi.x, hi.y);
        }
    }
}

// =====================================================================
// Fused epilogue: out = relu((relu(A)+relu(B)) @ W)
// =====================================================================
__global__ __launch_bounds__(256) void gemm64_fused(const float* __restrict__ A,
                                                    const float* __restrict__ B,
                                                    const float* __restrict__ W,
                                                    float* __restrict__ out, int N) {
    __shared__ __align__(16) float sW[64 * 64];
    __shared__ __align__(16) float sXT[128 * 64];
    int tid = threadIdx.x;
#pragma unroll
    for (int i = 0; i < 16; i++) sW[tid + i * 256] = W[tid + i * 256];
    long r0 = (long)blockIdx.x * 128;
#pragma unroll
    for (int i = 0; i < 32; i++) {
        int li = tid + i * 256;
        int row = li >> 6, col = li & 63;
        long gr = r0 + row;
        float v = 0.f;
        if (gr < N) {
            long idx = gr * 64 + col;
            v = fmaxf(A[idx], 0.f) + fmaxf(B[idx], 0.f);
        }
        sXT[col * 128 + (((row >> 2) ^ (col & 31)) << 2) + (row & 3)] = v;
    }
    __syncthreads();

    int tx = tid & 15, ty = tid >> 4;
    unsigned long long a1[8][2];
#pragma unroll
    for (int r = 0; r < 8; r++) { a1[r][0] = a1[r][1] = 0ull; }

    const float4* sXT4 = (const float4*)sXT;
    const ulonglong2* sWv = (const ulonglong2*)sW;
    int g0 = 2 * ty, g1 = 2 * ty + 1;
#pragma unroll 8
    for (int k = 0; k < 64; k++) {
        float4 xa = sXT4[k * 32 + (g0 ^ (k & 31))];
        float4 xb = sXT4[k * 32 + (g1 ^ (k & 31))];
        ulonglong2 w = sWv[k * 16 + tx];
        float xs[8] = {xa.x, xa.y, xa.z, xa.w, xb.x, xb.y, xb.z, xb.w};
#pragma unroll
        for (int r = 0; r < 8; r++) {
            unsigned long long xx = pack2(xs[r], xs[r]);
            fma2(a1[r][0], xx, w.x); fma2(a1[r][1], xx, w.y);
        }
    }
#pragma unroll
    for (int r = 0; r < 8; r++) {
        long row = r0 + ty * 8 + r;
        if (row < N) {
            float2 lo = unpack2(a1[r][0]), hi = unpack2(a1[r][1]);
            ((float4*)out)[row * 16 + tx] =
                make_float4(fmaxf(lo.x, 0.f), fmaxf(lo.y, 0.f),
                            fmaxf(hi.x, 0.f), fmaxf(hi.y, 0.f));
        }
    }
}

// =====================================================================
// Adjacency scatter, ILP-2: each thread processes its 16B slice of TWO
// independent edges (base+le and base+16+le).  Both gathers issue before
// either RED -> 2x outstanding long-latency loads per thread.
// E must be a multiple of 32 (1.5M / 800k both are).
// =====================================================================
__global__ __launch_bounds__(256) void scatter_edges2(const float* __restrict__ m,
                                                      const float* __restrict__ val,
                                                      const float* __restrict__ cci,
                                                      const float* __restrict__ a,
                                                      const int* __restrict__ src,
                                                      const int* __restrict__ dst,
                                                      float* __restrict__ acc, int E) {
    int base = blockIdx.x * 32;
    int tid = threadIdx.x;
    int le = tid >> 4, sub = tid & 15;
    int e0 = base + le;
    int e1 = base + 16 + le;

    float a0c = a[0], a1c = a[1], a2c = a[2];
    int s0 = src[e0], s1 = src[e1];
    int d0 = dst[e0], d1 = dst[e1];
    float c0 = val[e0] * (cci[e0 * 3 + 0] * a0c + cci[e0 * 3 + 1] * a1c + cci[e0 * 3 + 2] * a2c);
    float c1 = val[e1] * (cci[e1 * 3 + 0] * a0c + cci[e1 * 3 + 1] * a1c + cci[e1 * 3 + 2] * a2c);

    float4 v0 = reinterpret_cast<const float4*>(m + (long)s0 * 64)[sub];
    float4 v1 = reinterpret_cast<const float4*>(m + (long)s1 * 64)[sub];
    v0.x *= c0; v0.y *= c0; v0.z *= c0; v0.w *= c0;
    v1.x *= c1; v1.y *= c1; v1.z *= c1; v1.w *= c1;

    float* p0 = acc + (long)d0 * 64 + sub * 4;
    float* p1 = acc + (long)d1 * 64 + sub * 4;
    asm volatile("red.global.add.v4.f32 [%0], {%1,%2,%3,%4};"
                 :: "l"(p0), "f"(v0.x), "f"(v0.y), "f"(v0.z), "f"(v0.w) : "memory");
    asm volatile("red.global.add.v4.f32 [%0], {%1,%2,%3,%4};"
                 :: "l"(p1), "f"(v1.x), "f"(v1.y), "f"(v1.z), "f"(v1.w) : "memory");
}

// =====================================================================
// Incidence scatter, ILP-2 edges x 2 directions = 4 independent chains.
// =====================================================================
__global__ __launch_bounds__(256) void scatter_inc2(const float* __restrict__ ms,
                                                    const float* __restrict__ mt,
                                                    const int* __restrict__ row,
                                                    const int* __restrict__ col,
                                                    const float* __restrict__ val,
                                                    float* __restrict__ accB0,
                                                    float* __restrict__ accB1, int E) {
    int base = blockIdx.x * 32;
    int tid = threadIdx.x;
    int le = tid >> 4, sub = tid & 15;
    int e0 = base + le;
    int e1 = base + 16 + le;

    int r0 = row[e0], r1 = row[e1];
    int c0 = col[e0], c1 = col[e1];
    float v0 = val[e0], v1 = val[e1];

    // four independent gathers
    float4 a0 = reinterpret_cast<const float4*>(ms + (long)c0 * 64)[sub];
    float4 a1 = reinterpret_cast<const float4*>(ms + (long)c1 * 64)[sub];
    float4 b0 = reinterpret_cast<const float4*>(mt + (long)r0 * 64)[sub];
    float4 b1 = reinterpret_cast<const float4*>(mt + (long)r1 * 64)[sub];

    a0.x *= v0; a0.y *= v0; a0.z *= v0; a0.w *= v0;
    a1.x *= v1; a1.y *= v1; a1.z *= v1; a1.w *= v1;
    b0.x *= v0; b0.y *= v0; b0.z *= v0; b0.w *= v0;
    b1.x *= v1; b1.y *= v1; b1.z *= v1; b1.w *= v1;

    float* pa0 = accB0 + (long)r0 * 64 + sub * 4;
    float* pa1 = accB0 + (long)r1 * 64 + sub * 4;
    float* pb0 = accB1 + (long)c0 * 64 + sub * 4;
    float* pb1 = accB1 + (long)c1 * 64 + sub * 4;
    asm volatile("red.global.add.v4.f32 [%0], {%1,%2,%3,%4};"
                 :: "l"(pa0), "f"(a0.x), "f"(a0.y), "f"(a0.z), "f"(a0.w) : "memory");
    asm volatile("red.global.add.v4.f32 [%0], {%1,%2,%3,%4};"
                 :: "l"(pa1), "f"(a1.x), "f"(a1.y), "f"(a1.z), "f"(a1.w) : "memory");
    asm volatile("red.global.add.v4.f32 [%0], {%1,%2,%3,%4};"
                 :: "l"(pb0), "f"(b0.x), "f"(b0.y), "f"(b0.z), "f"(b0.w) : "memory");
    asm volatile("red.global.add.v4.f32 [%0], {%1,%2,%3,%4};"
                 :: "l"(pb1), "f"(b1.x), "f"(b1.y), "f"(b1.z), "f"(b1.w) : "memory");
}

// ---------------- stream/event pool: LAZY init on first kernel_launch ----------------
static cudaStream_t s1 = 0, s2 = 0, s3 = 0;
static cudaEvent_t eRoot = 0, eZ1 = 0, eZ = 0, eG0 = 0, eG1 = 0, eI = 0, eF0 = 0;
static int g_init_state = 0;  // 0 = untried, 1 = ok, -1 = failed (serial fallback)

static void ensure_init() {
    if (g_init_state != 0) return;
    bool ok = true;
    ok &= (cudaStreamCreateWithFlags(&s1, cudaStreamNonBlocking) == cudaSuccess);
    ok &= (cudaStreamCreateWithFlags(&s2, cudaStreamNonBlocking) == cudaSuccess);
    ok &= (cudaStreamCreateWithFlags(&s3, cudaStreamNonBlocking) == cudaSuccess);
    ok &= (cudaEventCreateWithFlags(&eRoot, cudaEventDisableTiming) == cudaSuccess);
    ok &= (cudaEventCreateWithFlags(&eZ1, cudaEventDisableTiming) == cudaSuccess);
    ok &= (cudaEventCreateWithFlags(&eZ, cudaEventDisableTiming) == cudaSuccess);
    ok &= (cudaEventCreateWithFlags(&eG0, cudaEventDisableTiming) == cudaSuccess);
    ok &= (cudaEventCreateWithFlags(&eG1, cudaEventDisableTiming) == cudaSuccess);
    ok &= (cudaEventCreateWithFlags(&eI, cudaEventDisableTiming) == cudaSuccess);
    ok &= (cudaEventCreateWithFlags(&eF0, cudaEventDisableTiming) == cudaSuccess);
    g_init_state = ok ? 1 : -1;
}

// ---------------- launch ----------------
extern "C" void kernel_launch(void* const* d_in, const int* in_sizes, int n_in,
                              void* d_out, int out_size) {
    ensure_init();

    const float* x0   = (const float*)d_in[0];
    const float* x1   = (const float*)d_in[1];
    const float* x2   = (const float*)d_in[2];
    const float* x3   = (const float*)d_in[3];
    const float* x4   = (const float*)d_in[4];
    const int*   adj0 = (const int*)d_in[5];
    const float* adj0v= (const float*)d_in[6];
    const int*   adj1 = (const int*)d_in[7];
    const float* adj1v= (const float*)d_in[8];
    const int*   inc  = (const int*)d_in[9];
    const float* incv = (const float*)d_in[10];
    const float* cci0 = (const float*)d_in[11];
    const float* cci1 = (const float*)d_in[12];
    const float* Whbs0= (const float*)d_in[13];
    const float* ahbs0= (const float*)d_in[14];
    const float* Whbs1= (const float*)d_in[15];
    const float* ahbs1= (const float*)d_in[16];
    const float* Ws   = (const float*)d_in[17];
    const float* Wt   = (const float*)d_in[18];
    const float* Wag0 = (const float*)d_in[19];
    const float* Wag1 = (const float*)d_in[20];
    float* out = (float*)d_out;

    float *pm0, *pm1, *pms, *pmt, *pA0, *pB0, *pA1, *pB1;
    cudaGetSymbolAddress((void**)&pm0, g_m0);
    cudaGetSymbolAddress((void**)&pm1, g_m1);
    cudaGetSymbolAddress((void**)&pms, g_ms);
    cudaGetSymbolAddress((void**)&pmt, g_mt);
    cudaGetSymbolAddress((void**)&pA0, g_accA0);
    cudaGetSymbolAddress((void**)&pB0, g_accB0);
    cudaGetSymbolAddress((void**)&pA1, g_accA1);
    cudaGetSymbolAddress((void**)&pB1, g_accB1);

    if (g_init_state == 1) {
        // ======== multi-stream overlapped schedule (R6 topology) ========
        cudaEventRecord(eRoot, 0);
        cudaStreamWaitEvent(s1, eRoot, 0);
        cudaStreamWaitEvent(s2, eRoot, 0);
        cudaStreamWaitEvent(s3, eRoot, 0);

        // s2: zero accumulators.  A1/B1 first so the big scatter starts ASAP.
        cudaMemsetAsync(pA1, 0, sizeof(float) * (size_t)CN1 * DD, s2);
        cudaMemsetAsync(pB1, 0, sizeof(float) * (size_t)CN1 * DD, s2);
        cudaEventRecord(eZ1, s2);
        cudaMemsetAsync(pA0, 0, sizeof(float) * (size_t)CN0 * DD, s2);
        cudaMemsetAsync(pB0, 0, sizeof(float) * (size_t)CN0 * DD, s2);
        cudaEventRecord(eZ, s2);

        // s1: chain0 — gemm(x0)
        gemm64_dual<<<(CN0 + 127) / 128, 256, 0, s1>>>(x0, Whbs0, Wt, pm0, pmt, CN0);
        cudaEventRecord(eG0, s1);

        // main: chain1 — gemm(x1)
        gemm64_dual<<<(CN1 + 127) / 128, 256, 0, 0>>>(x1, Whbs1, Ws, pm1, pms, CN1);
        cudaEventRecord(eG1, 0);

        // s3: pass-through copies, then scatter_inc (needs both gemms + zeros)
        cudaMemcpyAsync(out + (long)(CN0 + CN1) * DD, x2, sizeof(float) * (size_t)CN2 * DD,
                        cudaMemcpyDeviceToDevice, s3);
        cudaMemcpyAsync(out + (long)(CN0 + CN1 + CN2) * DD, x3, sizeof(float) * (size_t)CN3 * DD,
                        cudaMemcpyDeviceToDevice, s3);
        cudaMemcpyAsync(out + (long)(CN0 + CN1 + CN2 + CN3) * DD, x4,
                        sizeof(float) * (size_t)CN4 * DD, cudaMemcpyDeviceToDevice, s3);
        cudaStreamWaitEvent(s3, eG0, 0);
        cudaStreamWaitEvent(s3, eG1, 0);
        cudaStreamWaitEvent(s3, eZ, 0);
        scatter_inc2<<<CNNZ / 32, 256, 0, s3>>>(pms, pmt, inc, inc + CNNZ, incv,
                                                pB0, pB1, CNNZ);
        cudaEventRecord(eI, s3);

        // s1: scatter0 then fused0
        cudaStreamWaitEvent(s1, eZ, 0);
        scatter_edges2<<<CE0 / 32, 256, 0, s1>>>(pm0, adj0v, cci0, ahbs0,
                                                 adj0, adj0 + CE0, pA0, CE0);
        cudaStreamWaitEvent(s1, eI, 0);
        gemm64_fused<<<(CN0 + 127) / 128, 256, 0, s1>>>(pA0, pB0, Wag0, out, CN0);
        cudaEventRecord(eF0, s1);

        // main: scatter1 then fused1, then join
        cudaStreamWaitEvent(0, eZ1, 0);
        scatter_edges2<<<CE1 / 32, 256, 0, 0>>>(pm1, adj1v, cci1, ahbs1,
                                                adj1, adj1 + CE1, pA1, CE1);
        cudaStreamWaitEvent(0, eI, 0);
        gemm64_fused<<<(CN1 + 127) / 128, 256, 0, 0>>>(pA1, pB1, Wag1,
                                                       out + (long)CN0 * DD, CN1);
        cudaStreamWaitEvent(0, eF0, 0);  // joins s1 (s2/s3 ordered via eZ/eZ1/eI)
    } else {
        // ======== serial fallback ========
        cudaMemsetAsync(pA0, 0, sizeof(float) * (size_t)CN0 * DD);
        cudaMemsetAsync(pB0, 0, sizeof(float) * (size_t)CN0 * DD);
        cudaMemsetAsync(pA1, 0, sizeof(float) * (size_t)CN1 * DD);
        cudaMemsetAsync(pB1, 0, sizeof(float) * (size_t)CN1 * DD);
        gemm64_dual<<<(CN0 + 127) / 128, 256>>>(x0, Whbs0, Wt, pm0, pmt, CN0);
        gemm64_dual<<<(CN1 + 127) / 128, 256>>>(x1, Whbs1, Ws, pm1, pms, CN1);
        scatter_edges2<<<CE0 / 32, 256>>>(pm0, adj0v, cci0, ahbs0,
                                          adj0, adj0 + CE0, pA0, CE0);
        scatter_edges2<<<CE1 / 32, 256>>>(pm1, adj1v, cci1, ahbs1,
                                          adj1, adj1 + CE1, pA1, CE1);
        scatter_inc2<<<CNNZ / 32, 256>>>(pms, pmt, inc, inc + CNNZ, incv, pB0, pB1, CNNZ);
        gemm64_fused<<<(CN0 + 127) / 128, 256>>>(pA0, pB0, Wag0, out, CN0);
        gemm64_fused<<<(CN1 + 127) / 128, 256>>>(pA1, pB1, Wag1, out + (long)CN0 * DD, CN1);
        cudaMemcpyAsync(out + (long)(CN0 + CN1) * DD, x2, sizeof(float) * (size_t)CN2 * DD,
                        cudaMemcpyDeviceToDevice);
        cudaMemcpyAsync(out + (long)(CN0 + CN1 + CN2) * DD, x3, sizeof(float) * (size_t)CN3 * DD,
                        cudaMemcpyDeviceToDevice);
        cudaMemcpyAsync(out + (long)(CN0 + CN1 + CN2 + CN3) * DD, x4,
                        sizeof(float) * (size_t)CN4 * DD, cudaMemcpyDeviceToDevice);
    }
}

// round 11
// speedup vs baseline: 1.3046x; 1.0089x over previous
#include <cuda_runtime.h>

#define CN0 50000
#define CN1 150000
#define CN2 20000
#define CN3 5000
#define CN4 1000
#define CE0 800000
#define CE1 1500000
#define CNNZ 300000
#define DD 64

// ---------------- scratch (static device globals; no allocation) ----------------
__device__ float g_m0[CN0 * DD];
__device__ float g_m1[CN1 * DD];
__device__ float g_ms[CN1 * DD];
__device__ float g_mt[CN0 * DD];
__device__ float g_accA0[CN0 * DD];
__device__ float g_accB0[CN0 * DD];
__device__ float g_accA1[CN1 * DD];
__device__ float g_accB1[CN1 * DD];

// ---------------- packed f32x2 helpers (Blackwell FFMA2) ----------------
__device__ __forceinline__ unsigned long long pack2(float x, float y) {
    unsigned long long r;
    asm("mov.b64 %0, {%1,%2};" : "=l"(r) : "f"(x), "f"(y));
    return r;
}
__device__ __forceinline__ void fma2(unsigned long long& d, unsigned long long a,
                                     unsigned long long b) {
    asm("fma.rn.f32x2 %0, %1, %2, %0;" : "+l"(d) : "l"(a), "l"(b));
}
__device__ __forceinline__ float2 unpack2(unsigned long long v) {
    float2 f;
    asm("mov.b64 {%0,%1}, %2;" : "=f"(f.x), "=f"(f.y) : "l"(v));
    return f;
}

// =====================================================================
// Dual GEMM: out1 = X@W1, out2 = X@W2.  128 rows/block, 256 threads.
// =====================================================================
__global__ __launch_bounds__(256) void gemm64_dual(const float* __restrict__ X,
                                                   const float* __restrict__ W1,
                                                   const float* __restrict__ W2,
                                                   float* __restrict__ out1,
                                                   float* __restrict__ out2, int N) {
    __shared__ __align__(16) float sW1[64 * 64];
    __shared__ __align__(16) float sW2[64 * 64];
    __shared__ __align__(16) float sXT[128 * 64];
    int tid = threadIdx.x;
#pragma unroll
    for (int i = 0; i < 16; i++) {
        sW1[tid + i * 256] = W1[tid + i * 256];
        sW2[tid + i * 256] = W2[tid + i * 256];
    }
    long r0 = (long)blockIdx.x * 128;
#pragma unroll
    for (int i = 0; i < 32; i++) {
        int li = tid + i * 256;
        int row = li >> 6, col = li & 63;
        long gr = r0 + row;
        float v = (gr < N) ? X[gr * 64 + col] : 0.f;
        sXT[col * 128 + (((row >> 2) ^ (col & 31)) << 2) + (row & 3)] = v;
    }
    __syncthreads();

    int tx = tid & 15, ty = tid >> 4;
    unsigned long long a1[8][2], a2[8][2];
#pragma unroll
    for (int r = 0; r < 8; r++) { a1[r][0] = a1[r][1] = a2[r][0] = a2[r][1] = 0ull; }

    const float4* sXT4 = (const float4*)sXT;
    const ulonglong2* sW1v = (const ulonglong2*)sW1;
    const ulonglong2* sW2v = (const ulonglong2*)sW2;
    int g0 = 2 * ty, g1 = 2 * ty + 1;
#pragma unroll 8
    for (int k = 0; k < 64; k++) {
        float4 xa = sXT4[k * 32 + (g0 ^ (k & 31))];
        float4 xb = sXT4[k * 32 + (g1 ^ (k & 31))];
        ulonglong2 w1 = sW1v[k * 16 + tx];
        ulonglong2 w2 = sW2v[k * 16 + tx];
        float xs[8] = {xa.x, xa.y, xa.z, xa.w, xb.x, xb.y, xb.z, xb.w};
#pragma unroll
        for (int r = 0; r < 8; r++) {
            unsigned long long xx = pack2(xs[r], xs[r]);
            fma2(a1[r][0], xx, w1.x); fma2(a1[r][1], xx, w1.y);
            fma2(a2[r][0], xx, w2.x); fma2(a2[r][1], xx, w2.y);
        }
    }
#pragma unroll
    for (int r = 0; r < 8; r++) {
        long row = r0 + ty * 8 + r;
        if (row < N) {
            float2 lo = unpack2(a1[r][0]), hi = unpack2(a1[r][1]);
            ((float4*)out1)[row * 16 + tx] = make_float4(lo.x, lo.y, hi.x, hi.y);
            lo = unpack2(a2[r][0]); hi = unpack2(a2[r][1]);
            ((float4*)out2)[row * 16 + tx] = make_float4(lo.x, lo.y, hi.x, hi.y);
        }
    }
}

// =====================================================================
// Fused epilogue: out = relu((relu(A)+relu(B)) @ W)
// =====================================================================
__global__ __launch_bounds__(256) void gemm64_fused(const float* __restrict__ A,
                                                    const float* __restrict__ B,
                                                    const float* __restrict__ W,
                                                    float* __restrict__ out, int N) {
    __shared__ __align__(16) float sW[64 * 64];
    __shared__ __align__(16) float sXT[128 * 64];
    int tid = threadIdx.x;
#pragma unroll
    for (int i = 0; i < 16; i++) sW[tid + i * 256] = W[tid + i * 256];
    long r0 = (long)blockIdx.x * 128;
#pragma unroll
    for (int i = 0; i < 32; i++) {
        int li = tid + i * 256;
        int row = li >> 6, col = li & 63;
        long gr = r0 + row;
        float v = 0.f;
        if (gr < N) {
            long idx = gr * 64 + col;
            v = fmaxf(A[idx], 0.f) + fmaxf(B[idx], 0.f);
        }
        sXT[col * 128 + (((row >> 2) ^ (col & 31)) << 2) + (row & 3)] = v;
    }
    __syncthreads();

    int tx = tid & 15, ty = tid >> 4;
    unsigned long long a1[8][2];
#pragma unroll
    for (int r = 0; r < 8; r++) { a1[r][0] = a1[r][1] = 0ull; }

    const float4* sXT4 = (const float4*)sXT;
    const ulonglong2* sWv = (const ulonglong2*)sW;
    int g0 = 2 * ty, g1 = 2 * ty + 1;
#pragma unroll 8
    for (int k = 0; k < 64; k++) {
        float4 xa = sXT4[k * 32 + (g0 ^ (k & 31))];
        float4 xb = sXT4[k * 32 + (g1 ^ (k & 31))];
        ulonglong2 w = sWv[k * 16 + tx];
        float xs[8] = {xa.x, xa.y, xa.z, xa.w, xb.x, xb.y, xb.z, xb.w};
#pragma unroll
        for (int r = 0; r < 8; r++) {
            unsigned long long xx = pack2(xs[r], xs[r]);
            fma2(a1[r][0], xx, w.x); fma2(a1[r][1], xx, w.y);
        }
    }
#pragma unroll
    for (int r = 0; r < 8; r++) {
        long row = r0 + ty * 8 + r;
        if (row < N) {
            float2 lo = unpack2(a1[r][0]), hi = unpack2(a1[r][1]);
            ((float4*)out)[row * 16 + tx] =
                make_float4(fmaxf(lo.x, 0.f), fmaxf(lo.y, 0.f),
                            fmaxf(hi.x, 0.f), fmaxf(hi.y, 0.f));
        }
    }
}

// =====================================================================
// Adjacency scatter, ILP-4: each thread handles its 16B slice of FOUR
// independent edges (base + j*16 + le, j=0..3).  All gathers issue before
// any RED -> 4x outstanding long-latency loads per thread.
// Edges beyond E are predicated off (E1 isn't divisible by 64).
// =====================================================================
__global__ __launch_bounds__(256) void scatter_edges4(const float* __restrict__ m,
                                                      const float* __restrict__ val,
                                                      const float* __restrict__ cci,
                                                      const float* __restrict__ a,
                                                      const int* __restrict__ src,
                                                      const int* __restrict__ dst,
                                                      float* __restrict__ acc, int E) {
    int base = blockIdx.x * 64;
    int tid = threadIdx.x;
    int le = tid >> 4, sub = tid & 15;
    float a0c = a[0], a1c = a[1], a2c = a[2];

    int e[4];
    bool act[4];
    int s[4], d[4];
    float c[4];
#pragma unroll
    for (int j = 0; j < 4; j++) {
        e[j] = base + j * 16 + le;
        act[j] = (e[j] < E);
        int ee = act[j] ? e[j] : 0;
        s[j] = src[ee];
        d[j] = dst[ee];
        c[j] = val[ee] * (cci[ee * 3 + 0] * a0c + cci[ee * 3 + 1] * a1c +
                          cci[ee * 3 + 2] * a2c);
    }

    float4 v[4];
#pragma unroll
    for (int j = 0; j < 4; j++)
        v[j] = reinterpret_cast<const float4*>(m + (long)s[j] * 64)[sub];

#pragma unroll
    for (int j = 0; j < 4; j++) {
        v[j].x *= c[j]; v[j].y *= c[j]; v[j].z *= c[j]; v[j].w *= c[j];
        if (act[j]) {
            float* p = acc + (long)d[j] * 64 + sub * 4;
            asm volatile("red.global.add.v4.f32 [%0], {%1,%2,%3,%4};"
                         :: "l"(p), "f"(v[j].x), "f"(v[j].y), "f"(v[j].z), "f"(v[j].w)
                         : "memory");
        }
    }
}

// =====================================================================
// Incidence scatter, ILP-2 edges x 2 directions = 4 independent chains.
// =====================================================================
__global__ __launch_bounds__(256) void scatter_inc2(const float* __restrict__ ms,
                                                    const float* __restrict__ mt,
                                                    const int* __restrict__ row,
                                                    const int* __restrict__ col,
                                                    const float* __restrict__ val,
                                                    float* __restrict__ accB0,
                                                    float* __restrict__ accB1, int E) {
    int base = blockIdx.x * 32;
    int tid = threadIdx.x;
    int le = tid >> 4, sub = tid & 15;
    int e0 = base + le;
    int e1 = base + 16 + le;

    int r0 = row[e0], r1 = row[e1];
    int c0 = col[e0], c1 = col[e1];
    float v0 = val[e0], v1 = val[e1];

    float4 a0 = reinterpret_cast<const float4*>(ms + (long)c0 * 64)[sub];
    float4 a1 = reinterpret_cast<const float4*>(ms + (long)c1 * 64)[sub];
    float4 b0 = reinterpret_cast<const float4*>(mt + (long)r0 * 64)[sub];
    float4 b1 = reinterpret_cast<const float4*>(mt + (long)r1 * 64)[sub];

    a0.x *= v0; a0.y *= v0; a0.z *= v0; a0.w *= v0;
    a1.x *= v1; a1.y *= v1; a1.z *= v1; a1.w *= v1;
    b0.x *= v0; b0.y *= v0; b0.z *= v0; b0.w *= v0;
    b1.x *= v1; b1.y *= v1; b1.z *= v1; b1.w *= v1;

    float* pa0 = accB0 + (long)r0 * 64 + sub * 4;
    float* pa1 = accB0 + (long)r1 * 64 + sub * 4;
    float* pb0 = accB1 + (long)c0 * 64 + sub * 4;
    float* pb1 = accB1 + (long)c1 * 64 + sub * 4;
    asm volatile("red.global.add.v4.f32 [%0], {%1,%2,%3,%4};"
                 :: "l"(pa0), "f"(a0.x), "f"(a0.y), "f"(a0.z), "f"(a0.w) : "memory");
    asm volatile("red.global.add.v4.f32 [%0], {%1,%2,%3,%4};"
                 :: "l"(pa1), "f"(a1.x), "f"(a1.y), "f"(a1.z), "f"(a1.w) : "memory");
    asm volatile("red.global.add.v4.f32 [%0], {%1,%2,%3,%4};"
                 :: "l"(pb0), "f"(b0.x), "f"(b0.y), "f"(b0.z), "f"(b0.w) : "memory");
    asm volatile("red.global.add.v4.f32 [%0], {%1,%2,%3,%4};"
                 :: "l"(pb1), "f"(b1.x), "f"(b1.y), "f"(b1.z), "f"(b1.w) : "memory");
}

// ---------------- stream/event pool: LAZY init on first kernel_launch ----------------
static cudaStream_t s1 = 0, s2 = 0, s3 = 0;
static cudaEvent_t eRoot = 0, eZ1 = 0, eZ = 0, eG0 = 0, eG1 = 0, eI = 0, eF0 = 0;
static int g_init_state = 0;  // 0 = untried, 1 = ok, -1 = failed (serial fallback)

static void ensure_init() {
    if (g_init_state != 0) return;
    bool ok = true;
    ok &= (cudaStreamCreateWithFlags(&s1, cudaStreamNonBlocking) == cudaSuccess);
    ok &= (cudaStreamCreateWithFlags(&s2, cudaStreamNonBlocking) == cudaSuccess);
    ok &= (cudaStreamCreateWithFlags(&s3, cudaStreamNonBlocking) == cudaSuccess);
    ok &= (cudaEventCreateWithFlags(&eRoot, cudaEventDisableTiming) == cudaSuccess);
    ok &= (cudaEventCreateWithFlags(&eZ1, cudaEventDisableTiming) == cudaSuccess);
    ok &= (cudaEventCreateWithFlags(&eZ, cudaEventDisableTiming) == cudaSuccess);
    ok &= (cudaEventCreateWithFlags(&eG0, cudaEventDisableTiming) == cudaSuccess);
    ok &= (cudaEventCreateWithFlags(&eG1, cudaEventDisableTiming) == cudaSuccess);
    ok &= (cudaEventCreateWithFlags(&eI, cudaEventDisableTiming) == cudaSuccess);
    ok &= (cudaEventCreateWithFlags(&eF0, cudaEventDisableTiming) == cudaSuccess);
    g_init_state = ok ? 1 : -1;
}

// ---------------- launch ----------------
extern "C" void kernel_launch(void* const* d_in, const int* in_sizes, int n_in,
                              void* d_out, int out_size) {
    ensure_init();

    const float* x0   = (const float*)d_in[0];
    const float* x1   = (const float*)d_in[1];
    const float* x2   = (const float*)d_in[2];
    const float* x3   = (const float*)d_in[3];
    const float* x4   = (const float*)d_in[4];
    const int*   adj0 = (const int*)d_in[5];
    const float* adj0v= (const float*)d_in[6];
    const int*   adj1 = (const int*)d_in[7];
    const float* adj1v= (const float*)d_in[8];
    const int*   inc  = (const int*)d_in[9];
    const float* incv = (const float*)d_in[10];
    const float* cci0 = (const float*)d_in[11];
    const float* cci1 = (const float*)d_in[12];
    const float* Whbs0= (const float*)d_in[13];
    const float* ahbs0= (const float*)d_in[14];
    const float* Whbs1= (const float*)d_in[15];
    const float* ahbs1= (const float*)d_in[16];
    const float* Ws   = (const float*)d_in[17];
    const float* Wt   = (const float*)d_in[18];
    const float* Wag0 = (const float*)d_in[19];
    const float* Wag1 = (const float*)d_in[20];
    float* out = (float*)d_out;

    float *pm0, *pm1, *pms, *pmt, *pA0, *pB0, *pA1, *pB1;
    cudaGetSymbolAddress((void**)&pm0, g_m0);
    cudaGetSymbolAddress((void**)&pm1, g_m1);
    cudaGetSymbolAddress((void**)&pms, g_ms);
    cudaGetSymbolAddress((void**)&pmt, g_mt);
    cudaGetSymbolAddress((void**)&pA0, g_accA0);
    cudaGetSymbolAddress((void**)&pB0, g_accB0);
    cudaGetSymbolAddress((void**)&pA1, g_accA1);
    cudaGetSymbolAddress((void**)&pB1, g_accB1);

    if (g_init_state == 1) {
        // ======== multi-stream overlapped schedule (R9 topology) ========
        cudaEventRecord(eRoot, 0);
        cudaStreamWaitEvent(s1, eRoot, 0);
        cudaStreamWaitEvent(s2, eRoot, 0);
        cudaStreamWaitEvent(s3, eRoot, 0);

        // s2: zero accumulators.  A1/B1 first so the big scatter starts ASAP.
        cudaMemsetAsync(pA1, 0, sizeof(float) * (size_t)CN1 * DD, s2);
        cudaMemsetAsync(pB1, 0, sizeof(float) * (size_t)CN1 * DD, s2);
        cudaEventRecord(eZ1, s2);
        cudaMemsetAsync(pA0, 0, sizeof(float) * (size_t)CN0 * DD, s2);
        cudaMemsetAsync(pB0, 0, sizeof(float) * (size_t)CN0 * DD, s2);
        cudaEventRecord(eZ, s2);

        // s1: chain0 — gemm(x0)
        gemm64_dual<<<(CN0 + 127) / 128, 256, 0, s1>>>(x0, Whbs0, Wt, pm0, pmt, CN0);
        cudaEventRecord(eG0, s1);

        // main: chain1 — gemm(x1)
        gemm64_dual<<<(CN1 + 127) / 128, 256, 0, 0>>>(x1, Whbs1, Ws, pm1, pms, CN1);
        cudaEventRecord(eG1, 0);

        // s3: pass-through copies, then scatter_inc (needs both gemms + zeros)
        cudaMemcpyAsync(out + (long)(CN0 + CN1) * DD, x2, sizeof(float) * (size_t)CN2 * DD,
                        cudaMemcpyDeviceToDevice, s3);
        cudaMemcpyAsync(out + (long)(CN0 + CN1 + CN2) * DD, x3, sizeof(float) * (size_t)CN3 * DD,
                        cudaMemcpyDeviceToDevice, s3);
        cudaMemcpyAsync(out + (long)(CN0 + CN1 + CN2 + CN3) * DD, x4,
                        sizeof(float) * (size_t)CN4 * DD, cudaMemcpyDeviceToDevice, s3);
        cudaStreamWaitEvent(s3, eG0, 0);
        cudaStreamWaitEvent(s3, eG1, 0);
        cudaStreamWaitEvent(s3, eZ, 0);
        scatter_inc2<<<CNNZ / 32, 256, 0, s3>>>(pms, pmt, inc, inc + CNNZ, incv,
                                                pB0, pB1, CNNZ);
        cudaEventRecord(eI, s3);

        // s1: scatter0 then fused0
        cudaStreamWaitEvent(s1, eZ, 0);
        scatter_edges4<<<(CE0 + 63) / 64, 256, 0, s1>>>(pm0, adj0v, cci0, ahbs0,
                                                        adj0, adj0 + CE0, pA0, CE0);
        cudaStreamWaitEvent(s1, eI, 0);
        gemm64_fused<<<(CN0 + 127) / 128, 256, 0, s1>>>(pA0, pB0, Wag0, out, CN0);
        cudaEventRecord(eF0, s1);

        // main: scatter1 then fused1, then join
        cudaStreamWaitEvent(0, eZ1, 0);
        scatter_edges4<<<(CE1 + 63) / 64, 256, 0, 0>>>(pm1, adj1v, cci1, ahbs1,
                                                       adj1, adj1 + CE1, pA1, CE1);
        cudaStreamWaitEvent(0, eI, 0);
        gemm64_fused<<<(CN1 + 127) / 128, 256, 0, 0>>>(pA1, pB1, Wag1,
                                                       out + (long)CN0 * DD, CN1);
        cudaStreamWaitEvent(0, eF0, 0);  // joins s1 (s2/s3 ordered via eZ/eZ1/eI)
    } else {
        // ======== serial fallback ========
        cudaMemsetAsync(pA0, 0, sizeof(float) * (size_t)CN0 * DD);
        cudaMemsetAsync(pB0, 0, sizeof(float) * (size_t)CN0 * DD);
        cudaMemsetAsync(pA1, 0, sizeof(float) * (size_t)CN1 * DD);
        cudaMemsetAsync(pB1, 0, sizeof(float) * (size_t)CN1 * DD);
        gemm64_dual<<<(CN0 + 127) / 128, 256>>>(x0, Whbs0, Wt, pm0, pmt, CN0);
        gemm64_dual<<<(CN1 + 127) / 128, 256>>>(x1, Whbs1, Ws, pm1, pms, CN1);
        scatter_edges4<<<(CE0 + 63) / 64, 256>>>(pm0, adj0v, cci0, ahbs0,
                                                 adj0, adj0 + CE0, pA0, CE0);
        scatter_edges4<<<(CE1 + 63) / 64, 256>>>(pm1, adj1v, cci1, ahbs1,
                                                 adj1, adj1 + CE1, pA1, CE1);
        scatter_inc2<<<CNNZ / 32, 256>>>(pms, pmt, inc, inc + CNNZ, incv, pB0, pB1, CNNZ);
        gemm64_fused<<<(CN0 + 127) / 128, 256>>>(pA0, pB0, Wag0, out, CN0);
        gemm64_fused<<<(CN1 + 127) / 128, 256>>>(pA1, pB1, Wag1, out + (long)CN0 * DD, CN1);
        cudaMemcpyAsync(out + (long)(CN0 + CN1) * DD, x2, sizeof(float) * (size_t)CN2 * DD,
                        cudaMemcpyDeviceToDevice);
        cudaMemcpyAsync(out + (long)(CN0 + CN1 + CN2) * DD, x3, sizeof(float) * (size_t)CN3 * DD,
                        cudaMemcpyDeviceToDevice);
        cudaMemcpyAsync(out + (long)(CN0 + CN1 + CN2 + CN3) * DD, x4,
                        sizeof(float) * (size_t)CN4 * DD, cudaMemcpyDeviceToDevice);
    }
}